// round 5
// baseline (speedup 1.0000x reference)
#include <cuda_runtime.h>
#include <cuda_bf16.h>
#include <cstdint>
#include <cstddef>

#define BATCH 4
#define SEQ   2048
#define DIM   1024
#define NQKV  3072
#define SCALE 0.03125f   // 1024^-0.5

typedef __nv_bfloat16 bf16;

// ---------------------------------------------------------------------------
// Scratch (static device globals — allocation-free per harness rules)
// ---------------------------------------------------------------------------
__device__ bf16  g_Xh[(size_t)BATCH * SEQ * DIM];
__device__ bf16  g_Xl[(size_t)BATCH * SEQ * DIM];
__device__ bf16  g_Wh[(size_t)NQKV * DIM];
__device__ bf16  g_Wl[(size_t)NQKV * DIM];
__device__ bf16  g_Qh[(size_t)BATCH * SEQ * DIM];   // pre-scaled by SCALE
__device__ bf16  g_Ql[(size_t)BATCH * SEQ * DIM];
__device__ bf16  g_Kh[(size_t)BATCH * SEQ * DIM];
__device__ bf16  g_Kl[(size_t)BATCH * SEQ * DIM];
__device__ float g_V [(size_t)BATCH * SEQ * DIM];   // row-major fp32 V
__device__ bf16  g_Vth[(size_t)BATCH * DIM * SEQ];  // [b, d, t]
__device__ bf16  g_Vtl[(size_t)BATCH * DIM * SEQ];
__device__ float g_S [(size_t)BATCH * SEQ * SEQ];   // scores fp32
__device__ bf16  g_Ph[(size_t)BATCH * SEQ * SEQ];   // softmax probs hi/lo
__device__ bf16  g_Pl[(size_t)BATCH * SEQ * SEQ];

// ---------------------------------------------------------------------------
// helpers
// ---------------------------------------------------------------------------
__device__ __forceinline__ uint32_t smem_u32(const void* p) {
    uint32_t a;
    asm("{ .reg .u64 t; cvta.to.shared.u64 t, %1; cvt.u32.u64 %0, t; }"
        : "=r"(a) : "l"(p));
    return a;
}

__device__ __forceinline__ void ldm4(uint32_t addr, uint32_t& r0, uint32_t& r1,
                                     uint32_t& r2, uint32_t& r3) {
    asm volatile("ldmatrix.sync.aligned.m8n8.x4.shared.b16 {%0,%1,%2,%3}, [%4];"
                 : "=r"(r0), "=r"(r1), "=r"(r2), "=r"(r3) : "r"(addr));
}

__device__ __forceinline__ void mma16816(float* d, const uint32_t* a, const uint32_t* b) {
    asm volatile(
        "mma.sync.aligned.m16n8k16.row.col.f32.bf16.bf16.f32 "
        "{%0,%1,%2,%3}, {%4,%5,%6,%7}, {%8,%9}, {%0,%1,%2,%3};"
        : "+f"(d[0]), "+f"(d[1]), "+f"(d[2]), "+f"(d[3])
        : "r"(a[0]), "r"(a[1]), "r"(a[2]), "r"(a[3]), "r"(b[0]), "r"(b[1]));
}

__device__ __forceinline__ void cp16(uint32_t dst, const void* src) {
    asm volatile("cp.async.cg.shared.global [%0], [%1], 16;" :: "r"(dst), "l"(src));
}
__device__ __forceinline__ void cp_commit() {
    asm volatile("cp.async.commit_group;" ::: "memory");
}
__device__ __forceinline__ void cp_wait2() {
    asm volatile("cp.async.wait_group 2;" ::: "memory");
}
__device__ __forceinline__ void cp_wait0() {
    asm volatile("cp.async.wait_group 0;" ::: "memory");
}

// smem geometry: rows padded to 40 bf16 (80B) — conflict-free for ldmatrix
#define ROWB        80
#define MAT_BYTES   (128 * ROWB)                 // 10240 B (128 x 32 bf16 tile)
#define STAGE_BYTES (4 * MAT_BYTES)              // Ah | Al | Bh | Bl = 40960 B
#define NSTAGE      4
#define SMEM_BYTES  (NSTAGE * STAGE_BYTES)       // 163840 B

// ---------------------------------------------------------------------------
// cp.async one stage: A/B tiles (128 rows x 32 k, hi & lo) for k-block kb.
// thread t: row = t>>1, chunks (t&1)*2 + {0,1} of 16B (64B data per row).
// ---------------------------------------------------------------------------
__device__ __forceinline__ void issue_stage(const bf16* __restrict__ Ah,
                                            const bf16* __restrict__ Al,
                                            const bf16* __restrict__ Bh,
                                            const bf16* __restrict__ Bl,
                                            int K, int row0, int col0, int kb,
                                            uint32_t stg, int t) {
    const int r = t >> 1;
    const int c0 = (t & 1) * 2;
    const size_t aoff = (size_t)(row0 + r) * K + kb;
    const size_t boff = (size_t)(col0 + r) * K + kb;
    const uint32_t sr = stg + r * ROWB;
#pragma unroll
    for (int i = 0; i < 2; i++) {
        const int c = c0 + i;
        cp16(sr + c * 16,                 Ah + aoff + c * 8);
        cp16(sr + c * 16 + MAT_BYTES,     Al + aoff + c * 8);
        cp16(sr + c * 16 + 2 * MAT_BYTES, Bh + boff + c * 8);
        cp16(sr + c * 16 + 3 * MAT_BYTES, Bl + boff + c * 8);
    }
}

// ---------------------------------------------------------------------------
// bf16-split tensor-core GEMM: C[128,128] = A[M,K] * B[N,K]^T  (both K-major)
// 4-stage cp.async pipeline, one __syncthreads per K-iteration.
// MODE 0: X @ W^T  -> scatter to Qh/Ql(*SCALE), Kh/Kl, V(fp32 row-major)
// MODE 1: Q @ K^T  -> g_S      (per batch; scale pre-folded into Q)
// MODE 2: P @ Vt^T -> out      (per batch)
// ---------------------------------------------------------------------------
template <int MODE>
__global__ __launch_bounds__(256) void mma_gemm(float* __restrict__ Out) {
    extern __shared__ char smem[];
    const uint32_t sm = smem_u32(smem);
    const int t = threadIdx.x;
    const int wid = t >> 5;
    const int l = t & 31;
    const int z = blockIdx.z;

    const bf16 *Ah, *Al, *Bh, *Bl;
    float* C = nullptr;
    int K;
    if (MODE == 0) {
        Ah = g_Xh; Al = g_Xl; Bh = g_Wh; Bl = g_Wl; K = DIM;
    } else if (MODE == 1) {
        Ah = g_Qh + (size_t)z * SEQ * DIM;  Al = g_Ql + (size_t)z * SEQ * DIM;
        Bh = g_Kh + (size_t)z * SEQ * DIM;  Bl = g_Kl + (size_t)z * SEQ * DIM;
        C = g_S + (size_t)z * SEQ * SEQ;    K = DIM;
    } else {
        Ah = g_Ph + (size_t)z * SEQ * SEQ;  Al = g_Pl + (size_t)z * SEQ * SEQ;
        Bh = g_Vth + (size_t)z * DIM * SEQ; Bl = g_Vtl + (size_t)z * DIM * SEQ;
        C = Out + (size_t)z * SEQ * DIM;    K = SEQ;
    }

    const int row0 = blockIdx.y * 128;
    const int col0 = blockIdx.x * 128;
    const int KI = K / 32;

    const int wm = (wid >> 2) * 64;     // warp M offset
    const int wn = (wid & 3) * 32;      // warp N offset

    const int a_row = l & 15;
    const int a_koff = ((l >> 4) & 1) * 8;
    const int b_row = (l & 7) + ((l >> 4) & 1) * 8;
    const int b_koff = ((l >> 3) & 1) * 8;

    float acc[4][4][4];
#pragma unroll
    for (int mi = 0; mi < 4; mi++)
#pragma unroll
        for (int ni = 0; ni < 4; ni++)
#pragma unroll
            for (int j = 0; j < 4; j++) acc[mi][ni][j] = 0.0f;

    // prologue: fill stages 0..2
#pragma unroll
    for (int p = 0; p < NSTAGE - 1; p++) {
        issue_stage(Ah, Al, Bh, Bl, K, row0, col0, p * 32,
                    sm + p * STAGE_BYTES, t);
        cp_commit();
    }

    for (int it = 0; it < KI; it++) {
        const int s = it & (NSTAGE - 1);
        const uint32_t stg = sm + s * STAGE_BYTES;

        cp_wait2();            // stage s fill complete (this thread)
        __syncthreads();       // visibility to all warps; prev compute done

        // refill the stage freed by the previous iteration
        if (it + NSTAGE - 1 < KI)
            issue_stage(Ah, Al, Bh, Bl, K, row0, col0, (it + NSTAGE - 1) * 32,
                        sm + ((it + NSTAGE - 1) & (NSTAGE - 1)) * STAGE_BYTES, t);
        cp_commit();

        const uint32_t sAh = stg;
        const uint32_t sAl = stg + MAT_BYTES;
        const uint32_t sBh = stg + 2 * MAT_BYTES;
        const uint32_t sBl = stg + 3 * MAT_BYTES;
#pragma unroll
        for (int k0 = 0; k0 < 32; k0 += 16) {
            uint32_t bH[4][2], bL[4][2];
#pragma unroll
            for (int nb = 0; nb < 2; nb++) {
                const uint32_t off =
                    (uint32_t)((wn + nb * 16 + b_row) * ROWB + (k0 + b_koff) * 2);
                uint32_t r0, r1, r2, r3;
                ldm4(sBh + off, r0, r1, r2, r3);
                bH[2 * nb][0] = r0; bH[2 * nb][1] = r1;
                bH[2 * nb + 1][0] = r2; bH[2 * nb + 1][1] = r3;
                ldm4(sBl + off, r0, r1, r2, r3);
                bL[2 * nb][0] = r0; bL[2 * nb][1] = r1;
                bL[2 * nb + 1][0] = r2; bL[2 * nb + 1][1] = r3;
            }
#pragma unroll
            for (int mi = 0; mi < 4; mi++) {
                uint32_t aH[4], aL[4];
                const uint32_t off =
                    (uint32_t)((wm + mi * 16 + a_row) * ROWB + (k0 + a_koff) * 2);
                ldm4(sAh + off, aH[0], aH[1], aH[2], aH[3]);
                ldm4(sAl + off, aL[0], aL[1], aL[2], aL[3]);
#pragma unroll
                for (int ni = 0; ni < 4; ni++) {
                    mma16816(acc[mi][ni], aH, bH[ni]);
                    mma16816(acc[mi][ni], aH, bL[ni]);
                    mma16816(acc[mi][ni], aL, bH[ni]);
                }
            }
        }
    }

    cp_wait0();
    __syncthreads();           // safe to reuse smem for epilogue

    // Epilogue: fragments -> padded smem -> gmem
    float* Csh = (float*)smem;                     // 128 x 130 fp32 (66.6 KB)
#pragma unroll
    for (int mi = 0; mi < 4; mi++)
#pragma unroll
        for (int ni = 0; ni < 4; ni++) {
            const int r = wm + mi * 16 + (l >> 2);
            const int c = wn + ni * 8 + (l & 3) * 2;
            Csh[r * 130 + c]           = acc[mi][ni][0];
            Csh[r * 130 + c + 1]       = acc[mi][ni][1];
            Csh[(r + 8) * 130 + c]     = acc[mi][ni][2];
            Csh[(r + 8) * 130 + c + 1] = acc[mi][ni][3];
        }
    __syncthreads();

    for (int i = t; i < 128 * 128; i += 256) {
        const int r = i >> 7, c = i & 127;
        const float v = Csh[r * 130 + c];
        if (MODE == 0) {
            const int grow = row0 + r;
            const int col = col0 + c;
            const int which = col % 3;             // qkv reshape (d,3)
            const int oc = col / 3;
            const size_t o = (size_t)grow * DIM + oc;
            if (which == 0) {
                const float q = v * SCALE;         // fold attention scale into Q
                const bf16 h = __float2bfloat16(q);
                g_Qh[o] = h;
                g_Ql[o] = __float2bfloat16(q - __bfloat162float(h));
            } else if (which == 1) {
                const bf16 h = __float2bfloat16(v);
                g_Kh[o] = h;
                g_Kl[o] = __float2bfloat16(v - __bfloat162float(h));
            } else {
                g_V[o] = v;
            }
        } else if (MODE == 1) {
            C[(size_t)(row0 + r) * SEQ + col0 + c] = v;
        } else {
            C[(size_t)(row0 + r) * DIM + col0 + c] = v;
        }
    }
}

// ---------------------------------------------------------------------------
// Elementwise fp32 -> bf16 hi/lo split (8 elements per thread)
// ---------------------------------------------------------------------------
__global__ __launch_bounds__(256) void cvt_k(const float* __restrict__ src,
                                             bf16* __restrict__ dh,
                                             bf16* __restrict__ dl, int n8) {
    const int i = blockIdx.x * 256 + threadIdx.x;
    if (i >= n8) return;
    const float4 a = *(const float4*)(src + (size_t)i * 8);
    const float4 b = *(const float4*)(src + (size_t)i * 8 + 4);
    float x[8] = {a.x, a.y, a.z, a.w, b.x, b.y, b.z, b.w};
    bf16 h[8], lo[8];
#pragma unroll
    for (int j = 0; j < 8; j++) {
        h[j] = __float2bfloat16(x[j]);
        lo[j] = __float2bfloat16(x[j] - __bfloat162float(h[j]));
    }
    *(uint4*)(dh + (size_t)i * 8) = *(const uint4*)h;
    *(uint4*)(dl + (size_t)i * 8) = *(const uint4*)lo;
}

// ---------------------------------------------------------------------------
// V [b, t, d] fp32 -> Vt hi/lo [b, d, t] bf16 (32x32 smem tiles)
// ---------------------------------------------------------------------------
__global__ __launch_bounds__(256) void vtrans_k() {
    __shared__ float s[32][33];
    const int tx = threadIdx.x & 31;
    const int ty = threadIdx.x >> 5;      // 0..7
    const int t0 = blockIdx.x * 32;
    const int d0 = blockIdx.y * 32;
    const int z = blockIdx.z;
    const float* V = g_V + (size_t)z * SEQ * DIM;
#pragma unroll
    for (int i = 0; i < 4; i++) {
        const int r = ty + i * 8;
        s[r][tx] = V[(size_t)(t0 + r) * DIM + d0 + tx];
    }
    __syncthreads();
    bf16* Oh = g_Vth + (size_t)z * DIM * SEQ;
    bf16* Ol = g_Vtl + (size_t)z * DIM * SEQ;
#pragma unroll
    for (int i = 0; i < 4; i++) {
        const int dr = ty + i * 8;
        const float v = s[tx][dr];
        const bf16 h = __float2bfloat16(v);
        const size_t o = (size_t)(d0 + dr) * SEQ + t0 + tx;
        Oh[o] = h;
        Ol[o] = __float2bfloat16(v - __bfloat162float(h));
    }
}

// ---------------------------------------------------------------------------
// Row softmax: g_S row (2048 fp32) -> P hi/lo bf16. 8 consecutive per thread.
// ---------------------------------------------------------------------------
__global__ __launch_bounds__(256) void softmax_k() {
    const size_t base = (size_t)blockIdx.x * SEQ;
    const float* p = g_S + base;
    const int t = threadIdx.x;
    const int lane = t & 31;
    const int warp = t >> 5;
    __shared__ float red[2][8];

    const float4 a = *(const float4*)(p + t * 8);
    const float4 b = *(const float4*)(p + t * 8 + 4);
    float v[8] = {a.x, a.y, a.z, a.w, b.x, b.y, b.z, b.w};

    float m = -1e30f;
#pragma unroll
    for (int i = 0; i < 8; i++) m = fmaxf(m, v[i]);
#pragma unroll
    for (int off = 16; off > 0; off >>= 1)
        m = fmaxf(m, __shfl_xor_sync(0xffffffffu, m, off));
    if (lane == 0) red[0][warp] = m;
    __syncthreads();
    m = red[0][0];
#pragma unroll
    for (int w = 1; w < 8; w++) m = fmaxf(m, red[0][w]);

    float s = 0.0f;
#pragma unroll
    for (int i = 0; i < 8; i++) { v[i] = __expf(v[i] - m); s += v[i]; }
#pragma unroll
    for (int off = 16; off > 0; off >>= 1)
        s += __shfl_xor_sync(0xffffffffu, s, off);
    if (lane == 0) red[1][warp] = s;
    __syncthreads();
    s = red[1][0];
#pragma unroll
    for (int w = 1; w < 8; w++) s += red[1][w];

    const float inv = 1.0f / s;
    bf16 h[8], lo[8];
#pragma unroll
    for (int i = 0; i < 8; i++) {
        const float q = v[i] * inv;
        h[i] = __float2bfloat16(q);
        lo[i] = __float2bfloat16(q - __bfloat162float(h[i]));
    }
    *(uint4*)(g_Ph + base + t * 8) = *(const uint4*)h;
    *(uint4*)(g_Pl + base + t * 8) = *(const uint4*)lo;
}

// ---------------------------------------------------------------------------
extern "C" void kernel_launch(void* const* d_in, const int* in_sizes, int n_in,
                              void* d_out, int out_size) {
    const float* x = (const float*)d_in[0];    // [4, 2048, 1024]
    const float* W = (const float*)d_in[1];    // [3072, 1024]
    float* out = (float*)d_out;                // [4, 2048, 1024]

    cudaFuncSetAttribute(mma_gemm<0>, cudaFuncAttributeMaxDynamicSharedMemorySize, SMEM_BYTES);
    cudaFuncSetAttribute(mma_gemm<1>, cudaFuncAttributeMaxDynamicSharedMemorySize, SMEM_BYTES);
    cudaFuncSetAttribute(mma_gemm<2>, cudaFuncAttributeMaxDynamicSharedMemorySize, SMEM_BYTES);

    bf16 *Xh, *Xl, *Wh, *Wl;
    cudaGetSymbolAddress((void**)&Xh, g_Xh);
    cudaGetSymbolAddress((void**)&Xl, g_Xl);
    cudaGetSymbolAddress((void**)&Wh, g_Wh);
    cudaGetSymbolAddress((void**)&Wl, g_Wl);

    // 0) split inputs to bf16 hi/lo
    cvt_k<<<(BATCH * SEQ * DIM / 8 + 255) / 256, 256>>>(x, Xh, Xl, BATCH * SEQ * DIM / 8);
    cvt_k<<<(NQKV * DIM / 8 + 255) / 256, 256>>>(W, Wh, Wl, NQKV * DIM / 8);

    // 1) QKV projection (epilogue emits Q/K hi-lo and fp32 V)
    mma_gemm<0><<<dim3(NQKV / 128, (BATCH * SEQ) / 128, 1), 256, SMEM_BYTES>>>(nullptr);

    // 2) V transpose + split
    vtrans_k<<<dim3(SEQ / 32, DIM / 32, BATCH), 256>>>();

    // 3) scores = (Q*scale) K^T
    mma_gemm<1><<<dim3(SEQ / 128, SEQ / 128, BATCH), 256, SMEM_BYTES>>>(nullptr);

    // 4) softmax -> P hi/lo
    softmax_k<<<dim3(BATCH * SEQ), 256>>>();

    // 5) out = P V
    mma_gemm<2><<<dim3(DIM / 128, SEQ / 128, BATCH), 256, SMEM_BYTES>>>(out);
}

// round 6
// speedup vs baseline: 1.0513x; 1.0513x over previous
#include <cuda_runtime.h>
#include <cuda_bf16.h>
#include <cstdint>
#include <cstddef>

#define BATCH 4
#define SEQ   2048
#define DIM   1024
#define NQKV  3072
#define SCALE 0.03125f   // 1024^-0.5

typedef __nv_bfloat16 bf16;

// ---------------------------------------------------------------------------
// Scratch (static device globals — allocation-free per harness rules)
// ---------------------------------------------------------------------------
__device__ bf16  g_Xh[(size_t)BATCH * SEQ * DIM];
__device__ bf16  g_Xl[(size_t)BATCH * SEQ * DIM];
__device__ bf16  g_Wh[(size_t)NQKV * DIM];
__device__ bf16  g_Wl[(size_t)NQKV * DIM];
__device__ bf16  g_Qh[(size_t)BATCH * SEQ * DIM];   // pre-scaled by SCALE
__device__ bf16  g_Ql[(size_t)BATCH * SEQ * DIM];
__device__ bf16  g_Kh[(size_t)BATCH * SEQ * DIM];
__device__ bf16  g_Kl[(size_t)BATCH * SEQ * DIM];
__device__ float g_V [(size_t)BATCH * SEQ * DIM];   // row-major fp32 V
__device__ bf16  g_Vth[(size_t)BATCH * DIM * SEQ];  // [b, d, t]
__device__ bf16  g_Vtl[(size_t)BATCH * DIM * SEQ];
__device__ float g_S [(size_t)BATCH * SEQ * SEQ];   // scores fp32
__device__ bf16  g_Ph[(size_t)BATCH * SEQ * SEQ];   // softmax probs hi/lo
__device__ bf16  g_Pl[(size_t)BATCH * SEQ * SEQ];

// ---------------------------------------------------------------------------
// helpers
// ---------------------------------------------------------------------------
__device__ __forceinline__ uint32_t smem_u32(const void* p) {
    uint32_t a;
    asm("{ .reg .u64 t; cvta.to.shared.u64 t, %1; cvt.u32.u64 %0, t; }"
        : "=r"(a) : "l"(p));
    return a;
}

__device__ __forceinline__ void ldm4(uint32_t addr, uint32_t& r0, uint32_t& r1,
                                     uint32_t& r2, uint32_t& r3) {
    asm volatile("ldmatrix.sync.aligned.m8n8.x4.shared.b16 {%0,%1,%2,%3}, [%4];"
                 : "=r"(r0), "=r"(r1), "=r"(r2), "=r"(r3) : "r"(addr));
}

__device__ __forceinline__ void mma16816(float* d, const uint32_t* a, const uint32_t* b) {
    asm volatile(
        "mma.sync.aligned.m16n8k16.row.col.f32.bf16.bf16.f32 "
        "{%0,%1,%2,%3}, {%4,%5,%6,%7}, {%8,%9}, {%0,%1,%2,%3};"
        : "+f"(d[0]), "+f"(d[1]), "+f"(d[2]), "+f"(d[3])
        : "r"(a[0]), "r"(a[1]), "r"(a[2]), "r"(a[3]), "r"(b[0]), "r"(b[1]));
}

// smem geometry: rows padded to 40 bf16 (80B) — conflict-free for ldmatrix
#define ROWB        80
#define MAT_BYTES   (128 * ROWB)                 // 10240 B (128 x 32 bf16 tile)
#define STAGE_BYTES (4 * MAT_BYTES)              // Ah | Al | Bh | Bl = 40960 B
#define SMEM_BYTES  (2 * STAGE_BYTES)            // 81920 B (epilogue reuses)

// ---------------------------------------------------------------------------
// Register staging: thread t owns row r = t>>1, two 16B chunks (t&1)*2+{0,1}
// of the 64B row payload, for each of the 4 matrices (Ah, Al, Bh, Bl).
// ---------------------------------------------------------------------------
struct Stage {
    uint4 v[8];   // [mat*2 + chunk]: 0,1=Ah  2,3=Al  4,5=Bh  6,7=Bl
};

__device__ __forceinline__ void stage_load(Stage& st,
                                           const bf16* __restrict__ Ah,
                                           const bf16* __restrict__ Al,
                                           const bf16* __restrict__ Bh,
                                           const bf16* __restrict__ Bl,
                                           int K, int row0, int col0, int kb, int t) {
    const int r = t >> 1;
    const int c0 = (t & 1) * 2;
    const size_t aoff = (size_t)(row0 + r) * K + kb;
    const size_t boff = (size_t)(col0 + r) * K + kb;
#pragma unroll
    for (int i = 0; i < 2; i++) {
        const int c = c0 + i;
        st.v[0 + i] = *(const uint4*)(Ah + aoff + c * 8);
        st.v[2 + i] = *(const uint4*)(Al + aoff + c * 8);
        st.v[4 + i] = *(const uint4*)(Bh + boff + c * 8);
        st.v[6 + i] = *(const uint4*)(Bl + boff + c * 8);
    }
}

__device__ __forceinline__ void stage_store(const Stage& st, uint32_t stg, int t) {
    const int r = t >> 1;
    const int c0 = (t & 1) * 2;
    const uint32_t sr = stg + r * ROWB;
#pragma unroll
    for (int i = 0; i < 2; i++) {
        const int c = c0 + i;
#pragma unroll
        for (int m = 0; m < 4; m++) {
            const uint4 x = st.v[m * 2 + i];
            asm volatile("st.shared.v4.b32 [%0], {%1, %2, %3, %4};"
                         :: "r"(sr + m * MAT_BYTES + c * 16),
                            "r"(x.x), "r"(x.y), "r"(x.z), "r"(x.w));
        }
    }
}

// ---------------------------------------------------------------------------
// bf16-split tensor-core GEMM: C[128,128] = A[M,K] * B[N,K]^T  (both K-major)
// R3-style mainloop: LDG->regs prefetch, compute, STS, one sync per iter.
// MODE 0: X @ W^T  -> scatter to Qh/Ql(*SCALE), Kh/Kl, V(fp32 row-major)
// MODE 1: Q @ K^T  -> g_S      (per batch; scale pre-folded into Q)
// MODE 2: P @ Vt^T -> out      (per batch)
// ---------------------------------------------------------------------------
template <int MODE>
__global__ __launch_bounds__(256, 1) void mma_gemm(float* __restrict__ Out) {
    extern __shared__ char smem[];
    const uint32_t sm = smem_u32(smem);
    const int t = threadIdx.x;
    const int wid = t >> 5;
    const int l = t & 31;
    const int z = blockIdx.z;

    const bf16 *Ah, *Al, *Bh, *Bl;
    float* C = nullptr;
    int K;
    if (MODE == 0) {
        Ah = g_Xh; Al = g_Xl; Bh = g_Wh; Bl = g_Wl; K = DIM;
    } else if (MODE == 1) {
        Ah = g_Qh + (size_t)z * SEQ * DIM;  Al = g_Ql + (size_t)z * SEQ * DIM;
        Bh = g_Kh + (size_t)z * SEQ * DIM;  Bl = g_Kl + (size_t)z * SEQ * DIM;
        C = g_S + (size_t)z * SEQ * SEQ;    K = DIM;
    } else {
        Ah = g_Ph + (size_t)z * SEQ * SEQ;  Al = g_Pl + (size_t)z * SEQ * SEQ;
        Bh = g_Vth + (size_t)z * DIM * SEQ; Bl = g_Vtl + (size_t)z * DIM * SEQ;
        C = Out + (size_t)z * SEQ * DIM;    K = SEQ;
    }

    const int row0 = blockIdx.y * 128;
    const int col0 = blockIdx.x * 128;
    const int KI = K / 32;

    const int wm = (wid >> 2) * 64;     // warp M offset
    const int wn = (wid & 3) * 32;      // warp N offset

    const int a_row = l & 15;
    const int a_koff = ((l >> 4) & 1) * 8;
    const int b_row = (l & 7) + ((l >> 4) & 1) * 8;
    const int b_koff = ((l >> 3) & 1) * 8;

    float acc[4][4][4];
#pragma unroll
    for (int mi = 0; mi < 4; mi++)
#pragma unroll
        for (int ni = 0; ni < 4; ni++)
#pragma unroll
            for (int j = 0; j < 4; j++) acc[mi][ni][j] = 0.0f;

    Stage st;

    // prologue: stage 0
    stage_load(st, Ah, Al, Bh, Bl, K, row0, col0, 0, t);
    stage_store(st, sm, t);
    __syncthreads();

    for (int it = 0; it < KI; it++) {
        const int s = it & 1;
        const uint32_t stg = sm + s * STAGE_BYTES;
        const uint32_t nstg = sm + (1 - s) * STAGE_BYTES;

        // prefetch next k-block into registers (covers full compute below)
        if (it + 1 < KI)
            stage_load(st, Ah, Al, Bh, Bl, K, row0, col0, (it + 1) * 32, t);

        // compute on stage s
        const uint32_t sAh = stg;
        const uint32_t sAl = stg + MAT_BYTES;
        const uint32_t sBh = stg + 2 * MAT_BYTES;
        const uint32_t sBl = stg + 3 * MAT_BYTES;
#pragma unroll
        for (int k0 = 0; k0 < 32; k0 += 16) {
            uint32_t bH[4][2], bL[4][2];
#pragma unroll
            for (int nb = 0; nb < 2; nb++) {
                const uint32_t off =
                    (uint32_t)((wn + nb * 16 + b_row) * ROWB + (k0 + b_koff) * 2);
                uint32_t r0, r1, r2, r3;
                ldm4(sBh + off, r0, r1, r2, r3);
                bH[2 * nb][0] = r0; bH[2 * nb][1] = r1;
                bH[2 * nb + 1][0] = r2; bH[2 * nb + 1][1] = r3;
                ldm4(sBl + off, r0, r1, r2, r3);
                bL[2 * nb][0] = r0; bL[2 * nb][1] = r1;
                bL[2 * nb + 1][0] = r2; bL[2 * nb + 1][1] = r3;
            }
#pragma unroll
            for (int mi = 0; mi < 4; mi++) {
                uint32_t aH[4], aL[4];
                const uint32_t off =
                    (uint32_t)((wm + mi * 16 + a_row) * ROWB + (k0 + a_koff) * 2);
                ldm4(sAh + off, aH[0], aH[1], aH[2], aH[3]);
                ldm4(sAl + off, aL[0], aL[1], aL[2], aL[3]);
#pragma unroll
                for (int ni = 0; ni < 4; ni++) {
                    mma16816(acc[mi][ni], aH, bH[ni]);
                    mma16816(acc[mi][ni], aH, bL[ni]);
                    mma16816(acc[mi][ni], aL, bH[ni]);
                }
            }
        }

        if (it + 1 < KI)
            stage_store(st, nstg, t);
        __syncthreads();
    }

    // Epilogue: fragments -> padded smem -> gmem
    float* Csh = (float*)smem;                     // 128 x 130 fp32 (66.6 KB)
#pragma unroll
    for (int mi = 0; mi < 4; mi++)
#pragma unroll
        for (int ni = 0; ni < 4; ni++) {
            const int r = wm + mi * 16 + (l >> 2);
            const int c = wn + ni * 8 + (l & 3) * 2;
            Csh[r * 130 + c]           = acc[mi][ni][0];
            Csh[r * 130 + c + 1]       = acc[mi][ni][1];
            Csh[(r + 8) * 130 + c]     = acc[mi][ni][2];
            Csh[(r + 8) * 130 + c + 1] = acc[mi][ni][3];
        }
    __syncthreads();

    for (int i = t; i < 128 * 128; i += 256) {
        const int r = i >> 7, c = i & 127;
        const float v = Csh[r * 130 + c];
        if (MODE == 0) {
            const int grow = row0 + r;
            const int col = col0 + c;
            const int which = col % 3;             // qkv reshape (d,3)
            const int oc = col / 3;
            const size_t o = (size_t)grow * DIM + oc;
            if (which == 0) {
                const float q = v * SCALE;         // fold attention scale into Q
                const bf16 h = __float2bfloat16(q);
                g_Qh[o] = h;
                g_Ql[o] = __float2bfloat16(q - __bfloat162float(h));
            } else if (which == 1) {
                const bf16 h = __float2bfloat16(v);
                g_Kh[o] = h;
                g_Kl[o] = __float2bfloat16(v - __bfloat162float(h));
            } else {
                g_V[o] = v;
            }
        } else if (MODE == 1) {
            C[(size_t)(row0 + r) * SEQ + col0 + c] = v;
        } else {
            C[(size_t)(row0 + r) * DIM + col0 + c] = v;
        }
    }
}

// ---------------------------------------------------------------------------
// Elementwise fp32 -> bf16 hi/lo split (8 elements per thread)
// ---------------------------------------------------------------------------
__global__ __launch_bounds__(256) void cvt_k(const float* __restrict__ src,
                                             bf16* __restrict__ dh,
                                             bf16* __restrict__ dl, int n8) {
    const int i = blockIdx.x * 256 + threadIdx.x;
    if (i >= n8) return;
    const float4 a = *(const float4*)(src + (size_t)i * 8);
    const float4 b = *(const float4*)(src + (size_t)i * 8 + 4);
    float x[8] = {a.x, a.y, a.z, a.w, b.x, b.y, b.z, b.w};
    bf16 h[8], lo[8];
#pragma unroll
    for (int j = 0; j < 8; j++) {
        h[j] = __float2bfloat16(x[j]);
        lo[j] = __float2bfloat16(x[j] - __bfloat162float(h[j]));
    }
    *(uint4*)(dh + (size_t)i * 8) = *(const uint4*)h;
    *(uint4*)(dl + (size_t)i * 8) = *(const uint4*)lo;
}

// ---------------------------------------------------------------------------
// V [b, t, d] fp32 -> Vt hi/lo [b, d, t] bf16 (32x32 smem tiles)
// ---------------------------------------------------------------------------
__global__ __launch_bounds__(256) void vtrans_k() {
    __shared__ float s[32][33];
    const int tx = threadIdx.x & 31;
    const int ty = threadIdx.x >> 5;      // 0..7
    const int t0 = blockIdx.x * 32;
    const int d0 = blockIdx.y * 32;
    const int z = blockIdx.z;
    const float* V = g_V + (size_t)z * SEQ * DIM;
#pragma unroll
    for (int i = 0; i < 4; i++) {
        const int r = ty + i * 8;
        s[r][tx] = V[(size_t)(t0 + r) * DIM + d0 + tx];
    }
    __syncthreads();
    bf16* Oh = g_Vth + (size_t)z * DIM * SEQ;
    bf16* Ol = g_Vtl + (size_t)z * DIM * SEQ;
#pragma unroll
    for (int i = 0; i < 4; i++) {
        const int dr = ty + i * 8;
        const float v = s[tx][dr];
        const bf16 h = __float2bfloat16(v);
        const size_t o = (size_t)(d0 + dr) * SEQ + t0 + tx;
        Oh[o] = h;
        Ol[o] = __float2bfloat16(v - __bfloat162float(h));
    }
}

// ---------------------------------------------------------------------------
// Row softmax: g_S row (2048 fp32) -> P hi/lo bf16. 8 consecutive per thread.
// ---------------------------------------------------------------------------
__global__ __launch_bounds__(256) void softmax_k() {
    const size_t base = (size_t)blockIdx.x * SEQ;
    const float* p = g_S + base;
    const int t = threadIdx.x;
    const int lane = t & 31;
    const int warp = t >> 5;
    __shared__ float red[2][8];

    const float4 a = *(const float4*)(p + t * 8);
    const float4 b = *(const float4*)(p + t * 8 + 4);
    float v[8] = {a.x, a.y, a.z, a.w, b.x, b.y, b.z, b.w};

    float m = -1e30f;
#pragma unroll
    for (int i = 0; i < 8; i++) m = fmaxf(m, v[i]);
#pragma unroll
    for (int off = 16; off > 0; off >>= 1)
        m = fmaxf(m, __shfl_xor_sync(0xffffffffu, m, off));
    if (lane == 0) red[0][warp] = m;
    __syncthreads();
    m = red[0][0];
#pragma unroll
    for (int w = 1; w < 8; w++) m = fmaxf(m, red[0][w]);

    float s = 0.0f;
#pragma unroll
    for (int i = 0; i < 8; i++) { v[i] = __expf(v[i] - m); s += v[i]; }
#pragma unroll
    for (int off = 16; off > 0; off >>= 1)
        s += __shfl_xor_sync(0xffffffffu, s, off);
    if (lane == 0) red[1][warp] = s;
    __syncthreads();
    s = red[1][0];
#pragma unroll
    for (int w = 1; w < 8; w++) s += red[1][w];

    const float inv = 1.0f / s;
    bf16 h[8], lo[8];
#pragma unroll
    for (int i = 0; i < 8; i++) {
        const float q = v[i] * inv;
        h[i] = __float2bfloat16(q);
        lo[i] = __float2bfloat16(q - __bfloat162float(h[i]));
    }
    *(uint4*)(g_Ph + base + t * 8) = *(const uint4*)h;
    *(uint4*)(g_Pl + base + t * 8) = *(const uint4*)lo;
}

// ---------------------------------------------------------------------------
extern "C" void kernel_launch(void* const* d_in, const int* in_sizes, int n_in,
                              void* d_out, int out_size) {
    const float* x = (const float*)d_in[0];    // [4, 2048, 1024]
    const float* W = (const float*)d_in[1];    // [3072, 1024]
    float* out = (float*)d_out;                // [4, 2048, 1024]

    cudaFuncSetAttribute(mma_gemm<0>, cudaFuncAttributeMaxDynamicSharedMemorySize, SMEM_BYTES);
    cudaFuncSetAttribute(mma_gemm<1>, cudaFuncAttributeMaxDynamicSharedMemorySize, SMEM_BYTES);
    cudaFuncSetAttribute(mma_gemm<2>, cudaFuncAttributeMaxDynamicSharedMemorySize, SMEM_BYTES);

    bf16 *Xh, *Xl, *Wh, *Wl;
    cudaGetSymbolAddress((void**)&Xh, g_Xh);
    cudaGetSymbolAddress((void**)&Xl, g_Xl);
    cudaGetSymbolAddress((void**)&Wh, g_Wh);
    cudaGetSymbolAddress((void**)&Wl, g_Wl);

    // 0) split inputs to bf16 hi/lo
    cvt_k<<<(BATCH * SEQ * DIM / 8 + 255) / 256, 256>>>(x, Xh, Xl, BATCH * SEQ * DIM / 8);
    cvt_k<<<(NQKV * DIM / 8 + 255) / 256, 256>>>(W, Wh, Wl, NQKV * DIM / 8);

    // 1) QKV projection (epilogue emits Q/K hi-lo and fp32 V)
    mma_gemm<0><<<dim3(NQKV / 128, (BATCH * SEQ) / 128, 1), 256, SMEM_BYTES>>>(nullptr);

    // 2) V transpose + split
    vtrans_k<<<dim3(SEQ / 32, DIM / 32, BATCH), 256>>>();

    // 3) scores = (Q*scale) K^T
    mma_gemm<1><<<dim3(SEQ / 128, SEQ / 128, BATCH), 256, SMEM_BYTES>>>(nullptr);

    // 4) softmax -> P hi/lo
    softmax_k<<<dim3(BATCH * SEQ), 256>>>();

    // 5) out = P V
    mma_gemm<2><<<dim3(DIM / 128, SEQ / 128, BATCH), 256, SMEM_BYTES>>>(out);
}

// round 7
// speedup vs baseline: 1.1792x; 1.1217x over previous
#include <cuda_runtime.h>
#include <cuda_bf16.h>
#include <cstdint>
#include <cstddef>

#define BATCH 4
#define SEQ   2048
#define DIM   1024
#define NQKV  3072
#define SCALE 0.03125f   // 1024^-0.5

typedef __nv_bfloat16 bf16;

// ---------------------------------------------------------------------------
// Scratch (static device globals — allocation-free per harness rules)
// ---------------------------------------------------------------------------
__device__ bf16  g_Xh[(size_t)BATCH * SEQ * DIM];
__device__ bf16  g_Xl[(size_t)BATCH * SEQ * DIM];
__device__ bf16  g_Wh[(size_t)NQKV * DIM];
__device__ bf16  g_Wl[(size_t)NQKV * DIM];
__device__ bf16  g_Qh[(size_t)BATCH * SEQ * DIM];   // pre-scaled by SCALE
__device__ bf16  g_Ql[(size_t)BATCH * SEQ * DIM];
__device__ bf16  g_Kh[(size_t)BATCH * SEQ * DIM];
__device__ bf16  g_Kl[(size_t)BATCH * SEQ * DIM];
__device__ float g_V [(size_t)BATCH * SEQ * DIM];   // row-major fp32 V
__device__ bf16  g_Vth[(size_t)BATCH * DIM * SEQ];  // [b, d, t]
__device__ bf16  g_Vtl[(size_t)BATCH * DIM * SEQ];
__device__ float g_S [(size_t)BATCH * SEQ * SEQ];   // scores fp32
__device__ bf16  g_Ph[(size_t)BATCH * SEQ * SEQ];   // softmax probs hi/lo
__device__ bf16  g_Pl[(size_t)BATCH * SEQ * SEQ];

// ---------------------------------------------------------------------------
// helpers
// ---------------------------------------------------------------------------
__device__ __forceinline__ uint32_t smem_u32(const void* p) {
    uint32_t a;
    asm("{ .reg .u64 t; cvta.to.shared.u64 t, %1; cvt.u32.u64 %0, t; }"
        : "=r"(a) : "l"(p));
    return a;
}

__device__ __forceinline__ void ldm4(uint32_t addr, uint32_t& r0, uint32_t& r1,
                                     uint32_t& r2, uint32_t& r3) {
    asm volatile("ldmatrix.sync.aligned.m8n8.x4.shared.b16 {%0,%1,%2,%3}, [%4];"
                 : "=r"(r0), "=r"(r1), "=r"(r2), "=r"(r3) : "r"(addr));
}

__device__ __forceinline__ void mma16816(float* d, const uint32_t* a, const uint32_t* b) {
    asm volatile(
        "mma.sync.aligned.m16n8k16.row.col.f32.bf16.bf16.f32 "
        "{%0,%1,%2,%3}, {%4,%5,%6,%7}, {%8,%9}, {%0,%1,%2,%3};"
        : "+f"(d[0]), "+f"(d[1]), "+f"(d[2]), "+f"(d[3])
        : "r"(a[0]), "r"(a[1]), "r"(a[2]), "r"(a[3]), "r"(b[0]), "r"(b[1]));
}

// smem geometry: rows padded to 40 bf16 (80B) — conflict-free for ldmatrix
#define ROWB        80
#define MAT_BYTES   (128 * ROWB)                 // 10240 B (128 x 32 bf16 tile)
#define STAGE_BYTES (4 * MAT_BYTES)              // Ah | Al | Bh | Bl = 40960 B
#define SMEM_BYTES  (2 * STAGE_BYTES)            // 81920 B (epilogue reuses)

// ---------------------------------------------------------------------------
// Register staging, COALESCED mapping: 16B chunk fidx = t + i*256;
// row = fidx>>2 (4 threads per 64B row, contiguous within each warp LDG).
// ---------------------------------------------------------------------------
struct Stage {
    uint4 v[8];   // [mat*2 + i]: mat 0=Ah 1=Al 2=Bh 3=Bl ; i = pass 0/1
};

__device__ __forceinline__ void stage_load(Stage& st,
                                           const bf16* __restrict__ Ah,
                                           const bf16* __restrict__ Al,
                                           const bf16* __restrict__ Bh,
                                           const bf16* __restrict__ Bl,
                                           int K, int row0, int col0, int kb, int t) {
#pragma unroll
    for (int i = 0; i < 2; i++) {
        const int fidx = t + i * 256;
        const int r = fidx >> 2;          // 0..127
        const int c = fidx & 3;           // 16B chunk within 64B row payload
        const size_t aoff = (size_t)(row0 + r) * K + kb + c * 8;
        const size_t boff = (size_t)(col0 + r) * K + kb + c * 8;
        st.v[0 + i] = *(const uint4*)(Ah + aoff);
        st.v[2 + i] = *(const uint4*)(Al + aoff);
        st.v[4 + i] = *(const uint4*)(Bh + boff);
        st.v[6 + i] = *(const uint4*)(Bl + boff);
    }
}

__device__ __forceinline__ void stage_store(const Stage& st, uint32_t stg, int t) {
#pragma unroll
    for (int i = 0; i < 2; i++) {
        const int fidx = t + i * 256;
        const int r = fidx >> 2;
        const int c = fidx & 3;
        const uint32_t off = (uint32_t)(r * ROWB + c * 16);
#pragma unroll
        for (int m = 0; m < 4; m++) {
            const uint4 x = st.v[m * 2 + i];
            asm volatile("st.shared.v4.b32 [%0], {%1, %2, %3, %4};"
                         :: "r"(stg + m * MAT_BYTES + off),
                            "r"(x.x), "r"(x.y), "r"(x.z), "r"(x.w));
        }
    }
}

// ---------------------------------------------------------------------------
// bf16-split tensor-core GEMM: C[128,128] = A[M,K] * B[N,K]^T  (both K-major)
// R3-style mainloop: LDG->regs prefetch, compute, STS, one sync per iter.
// MODE 0: X @ W^T  -> scatter to Qh/Ql(*SCALE), Kh/Kl, V(fp32 row-major)
// MODE 1: Q @ K^T  -> g_S      (per batch; scale pre-folded into Q)
// MODE 2: P @ Vt^T -> out      (per batch)
// ---------------------------------------------------------------------------
template <int MODE>
__global__ __launch_bounds__(256, 1) void mma_gemm(float* __restrict__ Out) {
    extern __shared__ char smem[];
    const uint32_t sm = smem_u32(smem);
    const int t = threadIdx.x;
    const int wid = t >> 5;
    const int l = t & 31;
    const int z = blockIdx.z;

    const bf16 *Ah, *Al, *Bh, *Bl;
    float* C = nullptr;
    int K;
    if (MODE == 0) {
        Ah = g_Xh; Al = g_Xl; Bh = g_Wh; Bl = g_Wl; K = DIM;
    } else if (MODE == 1) {
        Ah = g_Qh + (size_t)z * SEQ * DIM;  Al = g_Ql + (size_t)z * SEQ * DIM;
        Bh = g_Kh + (size_t)z * SEQ * DIM;  Bl = g_Kl + (size_t)z * SEQ * DIM;
        C = g_S + (size_t)z * SEQ * SEQ;    K = DIM;
    } else {
        Ah = g_Ph + (size_t)z * SEQ * SEQ;  Al = g_Pl + (size_t)z * SEQ * SEQ;
        Bh = g_Vth + (size_t)z * DIM * SEQ; Bl = g_Vtl + (size_t)z * DIM * SEQ;
        C = Out + (size_t)z * SEQ * DIM;    K = SEQ;
    }

    const int row0 = blockIdx.y * 128;
    const int col0 = blockIdx.x * 128;
    const int KI = K / 32;

    const int wm = (wid >> 2) * 64;     // warp M offset
    const int wn = (wid & 3) * 32;      // warp N offset

    const int a_row = l & 15;
    const int a_koff = ((l >> 4) & 1) * 8;
    const int b_row = (l & 7) + ((l >> 4) & 1) * 8;
    const int b_koff = ((l >> 3) & 1) * 8;

    float acc[4][4][4];
#pragma unroll
    for (int mi = 0; mi < 4; mi++)
#pragma unroll
        for (int ni = 0; ni < 4; ni++)
#pragma unroll
            for (int j = 0; j < 4; j++) acc[mi][ni][j] = 0.0f;

    Stage st;

    // prologue: stage 0
    stage_load(st, Ah, Al, Bh, Bl, K, row0, col0, 0, t);
    stage_store(st, sm, t);
    __syncthreads();

    for (int it = 0; it < KI; it++) {
        const int s = it & 1;
        const uint32_t stg = sm + s * STAGE_BYTES;
        const uint32_t nstg = sm + (1 - s) * STAGE_BYTES;

        // prefetch next k-block into registers (covers full compute below)
        if (it + 1 < KI)
            stage_load(st, Ah, Al, Bh, Bl, K, row0, col0, (it + 1) * 32, t);

        // compute on stage s
        const uint32_t sAh = stg;
        const uint32_t sAl = stg + MAT_BYTES;
        const uint32_t sBh = stg + 2 * MAT_BYTES;
        const uint32_t sBl = stg + 3 * MAT_BYTES;
#pragma unroll
        for (int k0 = 0; k0 < 32; k0 += 16) {
            uint32_t bH[4][2], bL[4][2];
#pragma unroll
            for (int nb = 0; nb < 2; nb++) {
                const uint32_t off =
                    (uint32_t)((wn + nb * 16 + b_row) * ROWB + (k0 + b_koff) * 2);
                uint32_t r0, r1, r2, r3;
                ldm4(sBh + off, r0, r1, r2, r3);
                bH[2 * nb][0] = r0; bH[2 * nb][1] = r1;
                bH[2 * nb + 1][0] = r2; bH[2 * nb + 1][1] = r3;
                ldm4(sBl + off, r0, r1, r2, r3);
                bL[2 * nb][0] = r0; bL[2 * nb][1] = r1;
                bL[2 * nb + 1][0] = r2; bL[2 * nb + 1][1] = r3;
            }
#pragma unroll
            for (int mi = 0; mi < 4; mi++) {
                uint32_t aH[4], aL[4];
                const uint32_t off =
                    (uint32_t)((wm + mi * 16 + a_row) * ROWB + (k0 + a_koff) * 2);
                ldm4(sAh + off, aH[0], aH[1], aH[2], aH[3]);
                ldm4(sAl + off, aL[0], aL[1], aL[2], aL[3]);
#pragma unroll
                for (int ni = 0; ni < 4; ni++) {
                    mma16816(acc[mi][ni], aH, bH[ni]);
                    mma16816(acc[mi][ni], aH, bL[ni]);
                    mma16816(acc[mi][ni], aL, bH[ni]);
                }
            }
        }

        if (it + 1 < KI)
            stage_store(st, nstg, t);
        __syncthreads();
    }

    // Epilogue: fragments -> padded smem -> gmem
    float* Csh = (float*)smem;                     // 128 x 130 fp32 (66.6 KB)
#pragma unroll
    for (int mi = 0; mi < 4; mi++)
#pragma unroll
        for (int ni = 0; ni < 4; ni++) {
            const int r = wm + mi * 16 + (l >> 2);
            const int c = wn + ni * 8 + (l & 3) * 2;
            Csh[r * 130 + c]           = acc[mi][ni][0];
            Csh[r * 130 + c + 1]       = acc[mi][ni][1];
            Csh[(r + 8) * 130 + c]     = acc[mi][ni][2];
            Csh[(r + 8) * 130 + c + 1] = acc[mi][ni][3];
        }
    __syncthreads();

    for (int i = t; i < 128 * 128; i += 256) {
        const int r = i >> 7, c = i & 127;
        const float v = Csh[r * 130 + c];
        if (MODE == 0) {
            const int grow = row0 + r;
            const int col = col0 + c;
            const int which = col % 3;             // qkv reshape (d,3)
            const int oc = col / 3;
            const size_t o = (size_t)grow * DIM + oc;
            if (which == 0) {
                const float q = v * SCALE;         // fold attention scale into Q
                const bf16 h = __float2bfloat16(q);
                g_Qh[o] = h;
                g_Ql[o] = __float2bfloat16(q - __bfloat162float(h));
            } else if (which == 1) {
                const bf16 h = __float2bfloat16(v);
                g_Kh[o] = h;
                g_Kl[o] = __float2bfloat16(v - __bfloat162float(h));
            } else {
                g_V[o] = v;
            }
        } else if (MODE == 1) {
            C[(size_t)(row0 + r) * SEQ + col0 + c] = v;
        } else {
            C[(size_t)(row0 + r) * DIM + col0 + c] = v;
        }
    }
}

// ---------------------------------------------------------------------------
// Elementwise fp32 -> bf16 hi/lo split (8 elements per thread)
// ---------------------------------------------------------------------------
__global__ __launch_bounds__(256) void cvt_k(const float* __restrict__ src,
                                             bf16* __restrict__ dh,
                                             bf16* __restrict__ dl, int n8) {
    const int i = blockIdx.x * 256 + threadIdx.x;
    if (i >= n8) return;
    const float4 a = *(const float4*)(src + (size_t)i * 8);
    const float4 b = *(const float4*)(src + (size_t)i * 8 + 4);
    float x[8] = {a.x, a.y, a.z, a.w, b.x, b.y, b.z, b.w};
    bf16 h[8], lo[8];
#pragma unroll
    for (int j = 0; j < 8; j++) {
        h[j] = __float2bfloat16(x[j]);
        lo[j] = __float2bfloat16(x[j] - __bfloat162float(h[j]));
    }
    *(uint4*)(dh + (size_t)i * 8) = *(const uint4*)h;
    *(uint4*)(dl + (size_t)i * 8) = *(const uint4*)lo;
}

// ---------------------------------------------------------------------------
// V [b, t, d] fp32 -> Vt hi/lo [b, d, t] bf16 (32x32 smem tiles)
// ---------------------------------------------------------------------------
__global__ __launch_bounds__(256) void vtrans_k() {
    __shared__ float s[32][33];
    const int tx = threadIdx.x & 31;
    const int ty = threadIdx.x >> 5;      // 0..7
    const int t0 = blockIdx.x * 32;
    const int d0 = blockIdx.y * 32;
    const int z = blockIdx.z;
    const float* V = g_V + (size_t)z * SEQ * DIM;
#pragma unroll
    for (int i = 0; i < 4; i++) {
        const int r = ty + i * 8;
        s[r][tx] = V[(size_t)(t0 + r) * DIM + d0 + tx];
    }
    __syncthreads();
    bf16* Oh = g_Vth + (size_t)z * DIM * SEQ;
    bf16* Ol = g_Vtl + (size_t)z * DIM * SEQ;
#pragma unroll
    for (int i = 0; i < 4; i++) {
        const int dr = ty + i * 8;
        const float v = s[tx][dr];
        const bf16 h = __float2bfloat16(v);
        const size_t o = (size_t)(d0 + dr) * SEQ + t0 + tx;
        Oh[o] = h;
        Ol[o] = __float2bfloat16(v - __bfloat162float(h));
    }
}

// ---------------------------------------------------------------------------
// Row softmax: g_S row (2048 fp32) -> P hi/lo bf16. 8 consecutive per thread.
// ---------------------------------------------------------------------------
__global__ __launch_bounds__(256) void softmax_k() {
    const size_t base = (size_t)blockIdx.x * SEQ;
    const float* p = g_S + base;
    const int t = threadIdx.x;
    const int lane = t & 31;
    const int warp = t >> 5;
    __shared__ float red[2][8];

    const float4 a = *(const float4*)(p + t * 8);
    const float4 b = *(const float4*)(p + t * 8 + 4);
    float v[8] = {a.x, a.y, a.z, a.w, b.x, b.y, b.z, b.w};

    float m = -1e30f;
#pragma unroll
    for (int i = 0; i < 8; i++) m = fmaxf(m, v[i]);
#pragma unroll
    for (int off = 16; off > 0; off >>= 1)
        m = fmaxf(m, __shfl_xor_sync(0xffffffffu, m, off));
    if (lane == 0) red[0][warp] = m;
    __syncthreads();
    m = red[0][0];
#pragma unroll
    for (int w = 1; w < 8; w++) m = fmaxf(m, red[0][w]);

    float s = 0.0f;
#pragma unroll
    for (int i = 0; i < 8; i++) { v[i] = __expf(v[i] - m); s += v[i]; }
#pragma unroll
    for (int off = 16; off > 0; off >>= 1)
        s += __shfl_xor_sync(0xffffffffu, s, off);
    if (lane == 0) red[1][warp] = s;
    __syncthreads();
    s = red[1][0];
#pragma unroll
    for (int w = 1; w < 8; w++) s += red[1][w];

    const float inv = 1.0f / s;
    bf16 h[8], lo[8];
#pragma unroll
    for (int i = 0; i < 8; i++) {
        const float q = v[i] * inv;
        h[i] = __float2bfloat16(q);
        lo[i] = __float2bfloat16(q - __bfloat162float(h[i]));
    }
    *(uint4*)(g_Ph + base + t * 8) = *(const uint4*)h;
    *(uint4*)(g_Pl + base + t * 8) = *(const uint4*)lo;
}

// ---------------------------------------------------------------------------
extern "C" void kernel_launch(void* const* d_in, const int* in_sizes, int n_in,
                              void* d_out, int out_size) {
    const float* x = (const float*)d_in[0];    // [4, 2048, 1024]
    const float* W = (const float*)d_in[1];    // [3072, 1024]
    float* out = (float*)d_out;                // [4, 2048, 1024]

    cudaFuncSetAttribute(mma_gemm<0>, cudaFuncAttributeMaxDynamicSharedMemorySize, SMEM_BYTES);
    cudaFuncSetAttribute(mma_gemm<1>, cudaFuncAttributeMaxDynamicSharedMemorySize, SMEM_BYTES);
    cudaFuncSetAttribute(mma_gemm<2>, cudaFuncAttributeMaxDynamicSharedMemorySize, SMEM_BYTES);

    bf16 *Xh, *Xl, *Wh, *Wl;
    cudaGetSymbolAddress((void**)&Xh, g_Xh);
    cudaGetSymbolAddress((void**)&Xl, g_Xl);
    cudaGetSymbolAddress((void**)&Wh, g_Wh);
    cudaGetSymbolAddress((void**)&Wl, g_Wl);

    // 0) split inputs to bf16 hi/lo
    cvt_k<<<(BATCH * SEQ * DIM / 8 + 255) / 256, 256>>>(x, Xh, Xl, BATCH * SEQ * DIM / 8);
    cvt_k<<<(NQKV * DIM / 8 + 255) / 256, 256>>>(W, Wh, Wl, NQKV * DIM / 8);

    // 1) QKV projection (epilogue emits Q/K hi-lo and fp32 V)
    mma_gemm<0><<<dim3(NQKV / 128, (BATCH * SEQ) / 128, 1), 256, SMEM_BYTES>>>(nullptr);

    // 2) V transpose + split
    vtrans_k<<<dim3(SEQ / 32, DIM / 32, BATCH), 256>>>();

    // 3) scores = (Q*scale) K^T
    mma_gemm<1><<<dim3(SEQ / 128, SEQ / 128, BATCH), 256, SMEM_BYTES>>>(nullptr);

    // 4) softmax -> P hi/lo
    softmax_k<<<dim3(BATCH * SEQ), 256>>>();

    // 5) out = P V
    mma_gemm<2><<<dim3(DIM / 128, SEQ / 128, BATCH), 256, SMEM_BYTES>>>(out);
}

// round 8
// speedup vs baseline: 1.3319x; 1.1295x over previous
#include <cuda_runtime.h>
#include <cuda_bf16.h>
#include <cstdint>
#include <cstddef>

#define BATCH 4
#define SEQ   2048
#define DIM   1024
#define NQKV  3072
#define SCALE 0.03125f   // 1024^-0.5

// Scratch (static device globals — allocation-free per harness rules)
__device__ float g_Q [(size_t)BATCH * SEQ * DIM];   // [b*t, d]
__device__ float g_K [(size_t)BATCH * SEQ * DIM];   // [b*t, d]
__device__ float g_Vt[(size_t)BATCH * DIM * SEQ];   // [b, d, t] (transposed V)
__device__ float g_S [(size_t)BATCH * SEQ * SEQ];   // [b, t, t]

// ---------------------------------------------------------------------------
// helpers
// ---------------------------------------------------------------------------
__device__ __forceinline__ uint32_t smem_u32(const void* p) {
    uint32_t a;
    asm("{ .reg .u64 t; cvta.to.shared.u64 t, %1; cvt.u32.u64 %0, t; }"
        : "=r"(a) : "l"(p));
    return a;
}

__device__ __forceinline__ void ldm4(uint32_t addr, uint32_t& r0, uint32_t& r1,
                                     uint32_t& r2, uint32_t& r3) {
    asm volatile("ldmatrix.sync.aligned.m8n8.x4.shared.b16 {%0,%1,%2,%3}, [%4];"
                 : "=r"(r0), "=r"(r1), "=r"(r2), "=r"(r3) : "r"(addr));
}

__device__ __forceinline__ void mma16816(float* d, const uint32_t* a, const uint32_t* b) {
    asm volatile(
        "mma.sync.aligned.m16n8k16.row.col.f32.bf16.bf16.f32 "
        "{%0,%1,%2,%3}, {%4,%5,%6,%7}, {%8,%9}, {%0,%1,%2,%3};"
        : "+f"(d[0]), "+f"(d[1]), "+f"(d[2]), "+f"(d[3])
        : "r"(a[0]), "r"(a[1]), "r"(a[2]), "r"(a[3]), "r"(b[0]), "r"(b[1]));
}

// smem geometry: rows padded to 40 bf16 (80B) — conflict-free for ldmatrix
#define ROWB        80
#define A_MAT       (128 * ROWB)                 // 10240 B (128 x 32 bf16)
#define B_MAT       (64 * ROWB)                  // 5120 B  (64 x 32 bf16)
#define STAGE_BYTES (2 * A_MAT + 2 * B_MAT)      // Ah | Al | Bh | Bl = 30720 B
#define SMEM_BYTES  (2 * STAGE_BYTES)            // 61440 B (epilogue reuses)

// ---------------------------------------------------------------------------
// Register staging (128 threads): A tile 128x32 fp32 = 8 chunks/thread,
// B tile 64x32 fp32 = 4 chunks/thread. Chunk = 16B; fidx = t + i*128,
// r = fidx>>3, c = fidx&7 -> fully coalesced (8 threads per 128B row).
// ---------------------------------------------------------------------------
struct Stage {
    float4 a[8];
    float4 b[4];
};

__device__ __forceinline__ void stage_load(Stage& st,
                                           const float* __restrict__ A,
                                           const float* __restrict__ B,
                                           int K, int row0, int col0, int kb, int t) {
#pragma unroll
    for (int i = 0; i < 8; i++) {
        const int fidx = t + i * 128;
        const int r = fidx >> 3, c = fidx & 7;
        st.a[i] = *(const float4*)(A + (size_t)(row0 + r) * K + kb + c * 4);
    }
#pragma unroll
    for (int i = 0; i < 4; i++) {
        const int fidx = t + i * 128;
        const int r = fidx >> 3, c = fidx & 7;
        st.b[i] = *(const float4*)(B + (size_t)(col0 + r) * K + kb + c * 4);
    }
}

// convert one float4 chunk to hi/lo bf16x2 pairs and store (8B each)
__device__ __forceinline__ void cvt_st(const float4 v, uint32_t s_hi, uint32_t s_lo,
                                       uint32_t off) {
    uint32_t h0, h1, l0, l1;
    asm("cvt.rn.satfinite.bf16x2.f32 %0, %1, %2;" : "=r"(h0) : "f"(v.y), "f"(v.x));
    asm("cvt.rn.satfinite.bf16x2.f32 %0, %1, %2;" : "=r"(h1) : "f"(v.w), "f"(v.z));
    const float r0 = v.x - __uint_as_float(h0 << 16);
    const float r1 = v.y - __uint_as_float(h0 & 0xffff0000u);
    const float r2 = v.z - __uint_as_float(h1 << 16);
    const float r3 = v.w - __uint_as_float(h1 & 0xffff0000u);
    asm("cvt.rn.satfinite.bf16x2.f32 %0, %1, %2;" : "=r"(l0) : "f"(r1), "f"(r0));
    asm("cvt.rn.satfinite.bf16x2.f32 %0, %1, %2;" : "=r"(l1) : "f"(r3), "f"(r2));
    asm volatile("st.shared.v2.u32 [%0], {%1, %2};" :: "r"(s_hi + off), "r"(h0), "r"(h1));
    asm volatile("st.shared.v2.u32 [%0], {%1, %2};" :: "r"(s_lo + off), "r"(l0), "r"(l1));
}

__device__ __forceinline__ void stage_store(const Stage& st, uint32_t stg, int t) {
    const uint32_t sAh = stg;
    const uint32_t sAl = stg + A_MAT;
    const uint32_t sBh = stg + 2 * A_MAT;
    const uint32_t sBl = stg + 2 * A_MAT + B_MAT;
#pragma unroll
    for (int i = 0; i < 8; i++) {
        const int fidx = t + i * 128;
        const int r = fidx >> 3, c = fidx & 7;
        cvt_st(st.a[i], sAh, sAl, (uint32_t)(r * ROWB + c * 8));
    }
#pragma unroll
    for (int i = 0; i < 4; i++) {
        const int fidx = t + i * 128;
        const int r = fidx >> 3, c = fidx & 7;
        cvt_st(st.b[i], sBh, sBl, (uint32_t)(r * ROWB + c * 8));
    }
}

// ---------------------------------------------------------------------------
// bf16-split tensor-core GEMM: C[128,64] = A[M,K] * B[N,K]^T  (both K-major)
// 128 threads (4 warps), 2 CTAs/SM. R3-proven mainloop structure.
// MODE 0: X @ W^T  -> scatter to g_Q / g_K / g_Vt(transposed)
// MODE 1: Q @ K^T * scale -> g_S   (per batch)
// MODE 2: P @ Vt^T -> out          (per batch)
// ---------------------------------------------------------------------------
template <int MODE>
__global__ __launch_bounds__(128, 2) void mma_gemm(const float* __restrict__ X,
                                                   const float* __restrict__ W,
                                                   float* __restrict__ Out) {
    extern __shared__ char smem[];
    const uint32_t sm = smem_u32(smem);
    const int t = threadIdx.x;
    const int wid = t >> 5;
    const int l = t & 31;
    const int z = blockIdx.z;

    const float* A;
    const float* B;
    float* C = nullptr;
    int K;
    if (MODE == 0) { A = X; B = W; K = DIM; }
    else if (MODE == 1) {
        A = g_Q + (size_t)z * SEQ * DIM;
        B = g_K + (size_t)z * SEQ * DIM;
        C = g_S + (size_t)z * SEQ * SEQ;
        K = DIM;
    } else {
        A = g_S  + (size_t)z * SEQ * SEQ;
        B = g_Vt + (size_t)z * DIM * SEQ;
        C = Out  + (size_t)z * SEQ * DIM;
        K = SEQ;
    }

    const int row0 = blockIdx.y * 128;
    const int col0 = blockIdx.x * 64;
    const int KI = K / 32;

    const int wm = (wid >> 1) * 64;     // warp M offset (2x2 warp grid)
    const int wn = (wid & 1) * 32;      // warp N offset

    const int a_row = l & 15;
    const int a_koff = ((l >> 4) & 1) * 8;
    const int b_row = (l & 7) + ((l >> 4) & 1) * 8;
    const int b_koff = ((l >> 3) & 1) * 8;

    float acc[4][4][4];
#pragma unroll
    for (int mi = 0; mi < 4; mi++)
#pragma unroll
        for (int ni = 0; ni < 4; ni++)
#pragma unroll
            for (int j = 0; j < 4; j++) acc[mi][ni][j] = 0.0f;

    Stage st;

    // prologue: stage 0
    stage_load(st, A, B, K, row0, col0, 0, t);
    stage_store(st, sm, t);
    __syncthreads();

    for (int it = 0; it < KI; it++) {
        const int s = it & 1;
        const uint32_t stg = sm + s * STAGE_BYTES;
        const uint32_t nstg = sm + (1 - s) * STAGE_BYTES;

        // prefetch next k-block into registers (covers full compute below)
        if (it + 1 < KI)
            stage_load(st, A, B, K, row0, col0, (it + 1) * 32, t);

        // compute on stage s
        const uint32_t sAh = stg;
        const uint32_t sAl = stg + A_MAT;
        const uint32_t sBh = stg + 2 * A_MAT;
        const uint32_t sBl = stg + 2 * A_MAT + B_MAT;
#pragma unroll
        for (int k0 = 0; k0 < 32; k0 += 16) {
            uint32_t bH[4][2], bL[4][2];
#pragma unroll
            for (int nb = 0; nb < 2; nb++) {
                const uint32_t off =
                    (uint32_t)((wn + nb * 16 + b_row) * ROWB + (k0 + b_koff) * 2);
                uint32_t r0, r1, r2, r3;
                ldm4(sBh + off, r0, r1, r2, r3);
                bH[2 * nb][0] = r0; bH[2 * nb][1] = r1;
                bH[2 * nb + 1][0] = r2; bH[2 * nb + 1][1] = r3;
                ldm4(sBl + off, r0, r1, r2, r3);
                bL[2 * nb][0] = r0; bL[2 * nb][1] = r1;
                bL[2 * nb + 1][0] = r2; bL[2 * nb + 1][1] = r3;
            }
#pragma unroll
            for (int mi = 0; mi < 4; mi++) {
                uint32_t aH[4], aL[4];
                const uint32_t off =
                    (uint32_t)((wm + mi * 16 + a_row) * ROWB + (k0 + a_koff) * 2);
                ldm4(sAh + off, aH[0], aH[1], aH[2], aH[3]);
                ldm4(sAl + off, aL[0], aL[1], aL[2], aL[3]);
#pragma unroll
                for (int ni = 0; ni < 4; ni++) {
                    mma16816(acc[mi][ni], aH, bH[ni]);
                    mma16816(acc[mi][ni], aH, bL[ni]);
                    mma16816(acc[mi][ni], aL, bH[ni]);
                }
            }
        }

        if (it + 1 < KI)
            stage_store(st, nstg, t);
        __syncthreads();
    }

    // Epilogue: fragments -> padded smem -> (scatter) gmem
    float* Csh = (float*)smem;                     // 128 x 66 fp32 (33.8 KB)
#pragma unroll
    for (int mi = 0; mi < 4; mi++)
#pragma unroll
        for (int ni = 0; ni < 4; ni++) {
            const int r = wm + mi * 16 + (l >> 2);
            const int c = wn + ni * 8 + (l & 3) * 2;
            float d0 = acc[mi][ni][0], d1 = acc[mi][ni][1];
            float d2 = acc[mi][ni][2], d3 = acc[mi][ni][3];
            if (MODE == 1) { d0 *= SCALE; d1 *= SCALE; d2 *= SCALE; d3 *= SCALE; }
            Csh[r * 66 + c]           = d0;
            Csh[r * 66 + c + 1]       = d1;
            Csh[(r + 8) * 66 + c]     = d2;
            Csh[(r + 8) * 66 + c + 1] = d3;
        }
    __syncthreads();

    for (int i = t; i < 128 * 64; i += 128) {
        const int r = i >> 6, c = i & 63;
        const float v = Csh[r * 66 + c];
        if (MODE == 0) {
            const int grow = row0 + r;
            const int col = col0 + c;
            const int which = col % 3;             // qkv reshape (d,3)
            const int oc = col / 3;
            if (which == 0)      g_Q[(size_t)grow * DIM + oc] = v;
            else if (which == 1) g_K[(size_t)grow * DIM + oc] = v;
            else {
                const int b = grow >> 11, tt = grow & 2047;
                g_Vt[((size_t)b * DIM + oc) * SEQ + tt] = v;
            }
        } else if (MODE == 1) {
            C[(size_t)(row0 + r) * SEQ + col0 + c] = v;
        } else {
            C[(size_t)(row0 + r) * DIM + col0 + c] = v;
        }
    }
}

// ---------------------------------------------------------------------------
// Row softmax over g_S: one block (256 threads) per row of length 2048.
// ---------------------------------------------------------------------------
__global__ __launch_bounds__(256) void softmax_k() {
    float* p = g_S + (size_t)blockIdx.x * SEQ;
    const int t = threadIdx.x;
    const int lane = t & 31;
    const int warp = t >> 5;
    __shared__ float red[2][8];

    float v[8];
    float m = -1e30f;
#pragma unroll
    for (int i = 0; i < 8; i++) { v[i] = p[t + i * 256]; m = fmaxf(m, v[i]); }
#pragma unroll
    for (int off = 16; off > 0; off >>= 1)
        m = fmaxf(m, __shfl_xor_sync(0xffffffffu, m, off));
    if (lane == 0) red[0][warp] = m;
    __syncthreads();
    m = red[0][0];
#pragma unroll
    for (int w = 1; w < 8; w++) m = fmaxf(m, red[0][w]);

    float s = 0.0f;
#pragma unroll
    for (int i = 0; i < 8; i++) { v[i] = __expf(v[i] - m); s += v[i]; }
#pragma unroll
    for (int off = 16; off > 0; off >>= 1)
        s += __shfl_xor_sync(0xffffffffu, s, off);
    if (lane == 0) red[1][warp] = s;
    __syncthreads();
    s = red[1][0];
#pragma unroll
    for (int w = 1; w < 8; w++) s += red[1][w];

    const float inv = 1.0f / s;
#pragma unroll
    for (int i = 0; i < 8; i++) p[t + i * 256] = v[i] * inv;
}

// ---------------------------------------------------------------------------
extern "C" void kernel_launch(void* const* d_in, const int* in_sizes, int n_in,
                              void* d_out, int out_size) {
    const float* x = (const float*)d_in[0];    // [4, 2048, 1024]
    const float* W = (const float*)d_in[1];    // [3072, 1024]
    float* out = (float*)d_out;                // [4, 2048, 1024]

    cudaFuncSetAttribute(mma_gemm<0>, cudaFuncAttributeMaxDynamicSharedMemorySize, SMEM_BYTES);
    cudaFuncSetAttribute(mma_gemm<1>, cudaFuncAttributeMaxDynamicSharedMemorySize, SMEM_BYTES);
    cudaFuncSetAttribute(mma_gemm<2>, cudaFuncAttributeMaxDynamicSharedMemorySize, SMEM_BYTES);

    // 1) QKV projection (scatter epilogue de-interleaves into Q / K / V^T)
    mma_gemm<0><<<dim3(NQKV / 64, (BATCH * SEQ) / 128, 1), 128, SMEM_BYTES>>>(x, W, nullptr);
    // 2) scores = Q K^T * scale
    mma_gemm<1><<<dim3(SEQ / 64, SEQ / 128, BATCH), 128, SMEM_BYTES>>>(nullptr, nullptr, nullptr);
    // 3) row softmax
    softmax_k<<<dim3(BATCH * SEQ), 256>>>();
    // 4) out = P V
    mma_gemm<2><<<dim3(DIM / 64, SEQ / 128, BATCH), 128, SMEM_BYTES>>>(nullptr, nullptr, out);
}

// round 9
// speedup vs baseline: 1.3549x; 1.0173x over previous
#include <cuda_runtime.h>
#include <cuda_bf16.h>
#include <cstdint>
#include <cstddef>

#define BATCH 4
#define SEQ   2048
#define DIM   1024
#define NQKV  3072
#define SCALE 0.03125f   // 1024^-0.5

// Scratch (static device globals — allocation-free per harness rules)
__device__ float g_Q [(size_t)BATCH * SEQ * DIM];   // [b*t, d]
__device__ float g_K [(size_t)BATCH * SEQ * DIM];   // [b*t, d]
__device__ float g_Vt[(size_t)BATCH * DIM * SEQ];   // [b, d, t] (transposed V)
__device__ float g_S [(size_t)BATCH * SEQ * SEQ];   // [b, t, t]

// ---------------------------------------------------------------------------
// helpers
// ---------------------------------------------------------------------------
__device__ __forceinline__ uint32_t smem_u32(const void* p) {
    uint32_t a;
    asm("{ .reg .u64 t; cvta.to.shared.u64 t, %1; cvt.u32.u64 %0, t; }"
        : "=r"(a) : "l"(p));
    return a;
}

__device__ __forceinline__ void ldm4(uint32_t addr, uint32_t& r0, uint32_t& r1,
                                     uint32_t& r2, uint32_t& r3) {
    asm volatile("ldmatrix.sync.aligned.m8n8.x4.shared.b16 {%0,%1,%2,%3}, [%4];"
                 : "=r"(r0), "=r"(r1), "=r"(r2), "=r"(r3) : "r"(addr));
}

__device__ __forceinline__ void mma16816(float* d, const uint32_t* a, const uint32_t* b) {
    asm volatile(
        "mma.sync.aligned.m16n8k16.row.col.f32.bf16.bf16.f32 "
        "{%0,%1,%2,%3}, {%4,%5,%6,%7}, {%8,%9}, {%0,%1,%2,%3};"
        : "+f"(d[0]), "+f"(d[1]), "+f"(d[2]), "+f"(d[3])
        : "r"(a[0]), "r"(a[1]), "r"(a[2]), "r"(a[3]), "r"(b[0]), "r"(b[1]));
}

// smem geometry: rows padded to 40 bf16 (80B) — conflict-free for ldmatrix
#define ROWB        80
#define MAT_BYTES   (128 * ROWB)                 // 10240 B (128 x 32 bf16 tile)
#define STAGE_BYTES (4 * MAT_BYTES)              // Ah | Al | Bh | Bl = 40960 B
#define SMEM_BYTES  (2 * STAGE_BYTES)            // 81920 B; 2 CTAs = 160 KB/SM

// ---------------------------------------------------------------------------
// Half-stage register staging (128 threads): one 128x32 fp32 tile = 8 x 16B
// chunks per thread. fidx = t + i*128, r = fidx>>3, c = fidx&7 (coalesced,
// 8 threads per 128B row).
// ---------------------------------------------------------------------------
__device__ __forceinline__ void half_load(float4* v, const float* __restrict__ M,
                                          int K, int row0, int kb, int t) {
#pragma unroll
    for (int i = 0; i < 8; i++) {
        const int fidx = t + i * 128;
        const int r = fidx >> 3, c = fidx & 7;
        v[i] = *(const float4*)(M + (size_t)(row0 + r) * K + kb + c * 4);
    }
}

// convert one float4 chunk to hi/lo bf16x2 pairs and store (8B each)
__device__ __forceinline__ void cvt_st(const float4 v, uint32_t s_hi, uint32_t s_lo,
                                       uint32_t off) {
    uint32_t h0, h1, l0, l1;
    asm("cvt.rn.satfinite.bf16x2.f32 %0, %1, %2;" : "=r"(h0) : "f"(v.y), "f"(v.x));
    asm("cvt.rn.satfinite.bf16x2.f32 %0, %1, %2;" : "=r"(h1) : "f"(v.w), "f"(v.z));
    const float r0 = v.x - __uint_as_float(h0 << 16);
    const float r1 = v.y - __uint_as_float(h0 & 0xffff0000u);
    const float r2 = v.z - __uint_as_float(h1 << 16);
    const float r3 = v.w - __uint_as_float(h1 & 0xffff0000u);
    asm("cvt.rn.satfinite.bf16x2.f32 %0, %1, %2;" : "=r"(l0) : "f"(r1), "f"(r0));
    asm("cvt.rn.satfinite.bf16x2.f32 %0, %1, %2;" : "=r"(l1) : "f"(r3), "f"(r2));
    asm volatile("st.shared.v2.u32 [%0], {%1, %2};" :: "r"(s_hi + off), "r"(h0), "r"(h1));
    asm volatile("st.shared.v2.u32 [%0], {%1, %2};" :: "r"(s_lo + off), "r"(l0), "r"(l1));
}

__device__ __forceinline__ void half_store(const float4* v, uint32_t s_hi,
                                           uint32_t s_lo, int t) {
#pragma unroll
    for (int i = 0; i < 8; i++) {
        const int fidx = t + i * 128;
        const int r = fidx >> 3, c = fidx & 7;
        cvt_st(v[i], s_hi, s_lo, (uint32_t)(r * ROWB + c * 8));
    }
}

// ---------------------------------------------------------------------------
// bf16-split tensor-core GEMM: C[128,128] = A[M,K] * B[N,K]^T  (both K-major)
// 4 warps (warp tile 64x64), 128 threads, 2 CTAs/SM by construction.
// Split prefetch: A-half around k0=0 compute, B-half around k0=16.
// MODE 0: X @ W^T  -> scatter to g_Q / g_K / g_Vt(transposed)
// MODE 1: Q @ K^T * scale -> g_S   (per batch)
// MODE 2: P @ Vt^T -> out          (per batch)
// ---------------------------------------------------------------------------
template <int MODE>
__global__ __launch_bounds__(128) void mma_gemm(const float* __restrict__ X,
                                                const float* __restrict__ W,
                                                float* __restrict__ Out) {
    extern __shared__ char smem[];
    const uint32_t sm = smem_u32(smem);
    const int t = threadIdx.x;
    const int wid = t >> 5;
    const int l = t & 31;
    const int z = blockIdx.z;

    const float* A;
    const float* B;
    float* C = nullptr;
    int K;
    if (MODE == 0) { A = X; B = W; K = DIM; }
    else if (MODE == 1) {
        A = g_Q + (size_t)z * SEQ * DIM;
        B = g_K + (size_t)z * SEQ * DIM;
        C = g_S + (size_t)z * SEQ * SEQ;
        K = DIM;
    } else {
        A = g_S  + (size_t)z * SEQ * SEQ;
        B = g_Vt + (size_t)z * DIM * SEQ;
        C = Out  + (size_t)z * SEQ * DIM;
        K = SEQ;
    }

    const int row0 = blockIdx.y * 128;
    const int col0 = blockIdx.x * 128;
    const int KI = K / 32;

    const int wm = (wid >> 1) * 64;     // warp M offset (2x2 warp grid)
    const int wn = (wid & 1) * 64;      // warp N offset (64-wide!)

    const int a_row = l & 15;
    const int a_koff = ((l >> 4) & 1) * 8;
    const int b_row = (l & 7) + ((l >> 4) & 1) * 8;
    const int b_koff = ((l >> 3) & 1) * 8;

    float acc[4][8][4];                 // [mi][ni][frag] — 128 regs
#pragma unroll
    for (int mi = 0; mi < 4; mi++)
#pragma unroll
        for (int ni = 0; ni < 8; ni++)
#pragma unroll
            for (int j = 0; j < 4; j++) acc[mi][ni][j] = 0.0f;

    float4 pf[8];                       // half-stage prefetch buffer

    // prologue: stage 0 (A then B halves)
    half_load(pf, A, K, row0, 0, t);
    half_store(pf, sm, sm + MAT_BYTES, t);
    half_load(pf, B, K, col0, 0, t);
    half_store(pf, sm + 2 * MAT_BYTES, sm + 3 * MAT_BYTES, t);
    __syncthreads();

    for (int it = 0; it < KI; it++) {
        const int s = it & 1;
        const uint32_t stg = sm + s * STAGE_BYTES;
        const uint32_t nstg = sm + (1 - s) * STAGE_BYTES;
        const bool pfv = (it + 1 < KI);
        const int kb = (it + 1) * 32;

        // prefetch A-half for next iter (LDG latency covered by k0=0 compute)
        if (pfv) half_load(pf, A, K, row0, kb, t);

        const uint32_t sAh = stg;
        const uint32_t sAl = stg + MAT_BYTES;
        const uint32_t sBh = stg + 2 * MAT_BYTES;
        const uint32_t sBl = stg + 3 * MAT_BYTES;

#pragma unroll
        for (int k0 = 0; k0 < 32; k0 += 16) {
            uint32_t bH[8][2], bL[8][2];
#pragma unroll
            for (int nb = 0; nb < 4; nb++) {
                const uint32_t off =
                    (uint32_t)((wn + nb * 16 + b_row) * ROWB + (k0 + b_koff) * 2);
                uint32_t r0, r1, r2, r3;
                ldm4(sBh + off, r0, r1, r2, r3);
                bH[2 * nb][0] = r0; bH[2 * nb][1] = r1;
                bH[2 * nb + 1][0] = r2; bH[2 * nb + 1][1] = r3;
                ldm4(sBl + off, r0, r1, r2, r3);
                bL[2 * nb][0] = r0; bL[2 * nb][1] = r1;
                bL[2 * nb + 1][0] = r2; bL[2 * nb + 1][1] = r3;
            }
#pragma unroll
            for (int mi = 0; mi < 4; mi++) {
                uint32_t aH[4], aL[4];
                const uint32_t off =
                    (uint32_t)((wm + mi * 16 + a_row) * ROWB + (k0 + a_koff) * 2);
                ldm4(sAh + off, aH[0], aH[1], aH[2], aH[3]);
                ldm4(sAl + off, aL[0], aL[1], aL[2], aL[3]);
#pragma unroll
                for (int ni = 0; ni < 8; ni++) {
                    mma16816(acc[mi][ni], aH, bH[ni]);
                    mma16816(acc[mi][ni], aH, bL[ni]);
                    mma16816(acc[mi][ni], aL, bH[ni]);
                }
            }

            // between the two k0 steps: store A-half, start B-half prefetch
            if (k0 == 0 && pfv) {
                half_store(pf, nstg, nstg + MAT_BYTES, t);
                half_load(pf, B, K, col0, kb, t);
            }
        }

        if (pfv) half_store(pf, nstg + 2 * MAT_BYTES, nstg + 3 * MAT_BYTES, t);
        __syncthreads();
    }

    // Epilogue: fragments -> padded smem -> (scatter) gmem
    float* Csh = (float*)smem;                     // 128 x 130 fp32 (66.6 KB)
#pragma unroll
    for (int mi = 0; mi < 4; mi++)
#pragma unroll
        for (int ni = 0; ni < 8; ni++) {
            const int r = wm + mi * 16 + (l >> 2);
            const int c = wn + ni * 8 + (l & 3) * 2;
            float d0 = acc[mi][ni][0], d1 = acc[mi][ni][1];
            float d2 = acc[mi][ni][2], d3 = acc[mi][ni][3];
            if (MODE == 1) { d0 *= SCALE; d1 *= SCALE; d2 *= SCALE; d3 *= SCALE; }
            Csh[r * 130 + c]           = d0;
            Csh[r * 130 + c + 1]       = d1;
            Csh[(r + 8) * 130 + c]     = d2;
            Csh[(r + 8) * 130 + c + 1] = d3;
        }
    __syncthreads();

    for (int i = t; i < 128 * 128; i += 128) {
        const int r = i >> 7, c = i & 127;
        const float v = Csh[r * 130 + c];
        if (MODE == 0) {
            const int grow = row0 + r;
            const int col = col0 + c;
            const int which = col % 3;             // qkv reshape (d,3)
            const int oc = col / 3;
            if (which == 0)      g_Q[(size_t)grow * DIM + oc] = v;
            else if (which == 1) g_K[(size_t)grow * DIM + oc] = v;
            else {
                const int b = grow >> 11, tt = grow & 2047;
                g_Vt[((size_t)b * DIM + oc) * SEQ + tt] = v;
            }
        } else if (MODE == 1) {
            C[(size_t)(row0 + r) * SEQ + col0 + c] = v;
        } else {
            C[(size_t)(row0 + r) * DIM + col0 + c] = v;
        }
    }
}

// ---------------------------------------------------------------------------
// Row softmax over g_S: one block (256 threads) per row of length 2048.
// ---------------------------------------------------------------------------
__global__ __launch_bounds__(256) void softmax_k() {
    float* p = g_S + (size_t)blockIdx.x * SEQ;
    const int t = threadIdx.x;
    const int lane = t & 31;
    const int warp = t >> 5;
    __shared__ float red[2][8];

    float v[8];
    float m = -1e30f;
#pragma unroll
    for (int i = 0; i < 8; i++) { v[i] = p[t + i * 256]; m = fmaxf(m, v[i]); }
#pragma unroll
    for (int off = 16; off > 0; off >>= 1)
        m = fmaxf(m, __shfl_xor_sync(0xffffffffu, m, off));
    if (lane == 0) red[0][warp] = m;
    __syncthreads();
    m = red[0][0];
#pragma unroll
    for (int w = 1; w < 8; w++) m = fmaxf(m, red[0][w]);

    float s = 0.0f;
#pragma unroll
    for (int i = 0; i < 8; i++) { v[i] = __expf(v[i] - m); s += v[i]; }
#pragma unroll
    for (int off = 16; off > 0; off >>= 1)
        s += __shfl_xor_sync(0xffffffffu, s, off);
    if (lane == 0) red[1][warp] = s;
    __syncthreads();
    s = red[1][0];
#pragma unroll
    for (int w = 1; w < 8; w++) s += red[1][w];

    const float inv = 1.0f / s;
#pragma unroll
    for (int i = 0; i < 8; i++) p[t + i * 256] = v[i] * inv;
}

// ---------------------------------------------------------------------------
extern "C" void kernel_launch(void* const* d_in, const int* in_sizes, int n_in,
                              void* d_out, int out_size) {
    const float* x = (const float*)d_in[0];    // [4, 2048, 1024]
    const float* W = (const float*)d_in[1];    // [3072, 1024]
    float* out = (float*)d_out;                // [4, 2048, 1024]

    cudaFuncSetAttribute(mma_gemm<0>, cudaFuncAttributeMaxDynamicSharedMemorySize, SMEM_BYTES);
    cudaFuncSetAttribute(mma_gemm<1>, cudaFuncAttributeMaxDynamicSharedMemorySize, SMEM_BYTES);
    cudaFuncSetAttribute(mma_gemm<2>, cudaFuncAttributeMaxDynamicSharedMemorySize, SMEM_BYTES);

    // 1) QKV projection (scatter epilogue de-interleaves into Q / K / V^T)
    mma_gemm<0><<<dim3(NQKV / 128, (BATCH * SEQ) / 128, 1), 128, SMEM_BYTES>>>(x, W, nullptr);
    // 2) scores = Q K^T * scale
    mma_gemm<1><<<dim3(SEQ / 128, SEQ / 128, BATCH), 128, SMEM_BYTES>>>(nullptr, nullptr, nullptr);
    // 3) row softmax
    softmax_k<<<dim3(BATCH * SEQ), 256>>>();
    // 4) out = P V
    mma_gemm<2><<<dim3(DIM / 128, SEQ / 128, BATCH), 128, SMEM_BYTES>>>(nullptr, nullptr, out);
}